// round 10
// baseline (speedup 1.0000x reference)
#include <cuda_runtime.h>
#include <cuda_bf16.h>

// LengthRegulator, source-row-centric single kernel.
// out[b,t,:] = x[b, idx(t), :] where idx = searchsorted(cumsum(dur[b]), t, 'right'),
// zeroed where t >= total[b]. mel_mask appended to d_out as float 0/1.
//
// Inversion: t in [cum[j-1], cum[j]) has idx(t) == j exactly. So warp j loads
// source row j ONCE (3 float4/lane) and streams it dur[j] times. Rows
// t >= total are zero-filled by per-warp candidate ranges. This reads each
// x row once (48 MiB) instead of once per replica (192 MiB) -> L2 relief.

#define BB 32
#define NN 1024
#define DD 384
#define ML 4096
#define D4 (DD / 4)            // 96 float4 per row
#define NROWS (BB * ML)
#define TPB 1024
#define KPB 32                 // blocks per batch; each block owns 32 source rows

__global__ void __launch_bounds__(TPB) fused_kernel(
    const float4* __restrict__ x4,
    float4* __restrict__ out4,
    const int* __restrict__ dur,
    float* __restrict__ mask_out,
    int write_mask
) {
    const int b    = blockIdx.x >> 5;          // / KPB
    const int k    = blockIdx.x & (KPB - 1);
    const int tid  = threadIdx.x;
    const int lane = tid & 31;
    const int w    = tid >> 5;

    __shared__ int s_cum[NN];
    __shared__ int wsum[32];

    // ---- full-batch inclusive scan: 1024 threads, 1 duration each ----
    int inc = dur[b * NN + tid];
    #pragma unroll
    for (int o = 1; o < 32; o <<= 1) {
        int n = __shfl_up_sync(0xFFFFFFFFu, inc, o);
        if (lane >= o) inc += n;
    }
    if (lane == 31) wsum[w] = inc;
    __syncthreads();
    if (w == 0) {
        int s = wsum[lane];
        #pragma unroll
        for (int o = 1; o < 32; o <<= 1) {
            int n = __shfl_up_sync(0xFFFFFFFFu, s, o);
            if (lane >= o) s += n;
        }
        wsum[lane] = s;
    }
    __syncthreads();
    const int cum = inc + ((w > 0) ? wsum[w - 1] : 0);
    s_cum[tid] = cum;
    __syncthreads();

    const int total = s_cum[NN - 1];

    // ---- expansion: warp w of block k owns source row j ----
    const int j  = k * 32 + w;
    int lo = (j > 0) ? s_cum[j - 1] : 0;
    int hi = s_cum[j];
    lo = (lo < ML) ? lo : ML;
    hi = (hi < ML) ? hi : ML;

    if (hi > lo) {
        const float4* __restrict__ src = x4 + ((size_t)b * NN + j) * D4;
        const float4 v0 = src[lane];
        const float4 v1 = src[lane + 32];
        const float4 v2 = src[lane + 64];

        float4* d = out4 + ((size_t)b * ML + lo) * D4;
        for (int t = lo; t < hi; t++) {
            __stcs(d + lane,      v0);
            __stcs(d + lane + 32, v1);
            __stcs(d + lane + 64, v2);
            d += D4;
        }
    }

    // ---- zero-fill + mask: warp u owns output rows [4u, 4u+4) ----
    const int u  = k * 32 + w;          // 0..1023 within batch
    const int t0 = 4 * u;

    if (write_mask && lane == 0) {
        float4 mv;
        mv.x = (float)(t0 + 0 >= total);
        mv.y = (float)(t0 + 1 >= total);
        mv.z = (float)(t0 + 2 >= total);
        mv.w = (float)(t0 + 3 >= total);
        __stcs((float4*)(mask_out + (size_t)b * ML + t0), mv);
    }

    const float4 z = make_float4(0.f, 0.f, 0.f, 0.f);
    #pragma unroll
    for (int r = 0; r < 4; r++) {
        const int t = t0 + r;
        if (t >= total) {
            float4* d = out4 + ((size_t)b * ML + t) * D4;
            __stcs(d + lane,      z);
            __stcs(d + lane + 32, z);
            __stcs(d + lane + 64, z);
        }
    }
}

extern "C" void kernel_launch(void* const* d_in, const int* in_sizes, int n_in,
                              void* d_out, int out_size) {
    const float* x   = (const float*)d_in[0];
    const int*   dur = (const int*)d_in[1];
    float*       out = (float*)d_out;

    const long long out_elems  = (long long)NROWS * DD;
    const long long mask_elems = (long long)NROWS;
    int write_mask = ((long long)out_size >= out_elems + mask_elems) ? 1 : 0;
    float* mask_out = write_mask ? (out + out_elems) : nullptr;

    fused_kernel<<<BB * KPB, TPB>>>((const float4*)x, (float4*)out, dur,
                                    mask_out, write_mask);
}

// round 11
// speedup vs baseline: 1.0772x; 1.0772x over previous
#include <cuda_runtime.h>
#include <cuda_bf16.h>

// LengthRegulator, fused single kernel (gather form, load-deduped).
// out[b,t,:] = x[b, searchsorted(cumsum(dur[b]), t, 'right'), :], zeroed where
// t >= total[b]. mel_mask appended to d_out as float 0/1.

#define BB 32
#define NN 1024
#define DD 384
#define ML 4096
#define D4 (DD / 4)            // 96 float4 per row
#define NROWS (BB * ML)        // 131072 output rows
#define TPB 256
#define ROWS_PB 32             // rows per block (8 warps x 4 rows)
#define BPB (ML / ROWS_PB)     // 128 blocks per batch

__global__ void __launch_bounds__(TPB) fused_kernel(
    const float4* __restrict__ x4,
    float4* __restrict__ out4,
    const int* __restrict__ dur,
    float* __restrict__ mask_out,
    int write_mask
) {
    const int b    = blockIdx.x >> 7;       // / BPB
    const int seg  = blockIdx.x & (BPB - 1);
    const int tid  = threadIdx.x;
    const int lane = tid & 31;
    const int w    = tid >> 5;

    __shared__ int s_cum[NN];
    __shared__ int wsum[8];

    // ---- block scan of 1024 durations (4 per thread via int4) ----
    int4 dv = ((const int4*)(dur + b * NN))[tid];
    const int a0 = dv.x;
    const int a1 = a0 + dv.y;
    const int a2 = a1 + dv.z;
    const int a3 = a2 + dv.w;
    const int tsum = a3;

    int inc = tsum;
    #pragma unroll
    for (int o = 1; o < 32; o <<= 1) {
        int n = __shfl_up_sync(0xFFFFFFFFu, inc, o);
        if (lane >= o) inc += n;
    }
    if (lane == 31) wsum[w] = inc;
    __syncthreads();

    int woff = 0;
    #pragma unroll
    for (int i = 0; i < 8; i++) {
        int wv = wsum[i];
        woff += (i < w) ? wv : 0;
    }
    const int base = woff + (inc - tsum);   // exclusive prefix for this thread

    s_cum[4 * tid + 0] = base + a0;
    s_cum[4 * tid + 1] = base + a1;
    s_cum[4 * tid + 2] = base + a2;
    s_cum[4 * tid + 3] = base + a3;
    __syncthreads();

    const int total = s_cum[NN - 1];

    // ---- searches: warp w owns rows tloc0..tloc0+3; lane (lane&3) searches ----
    const int tloc0 = seg * ROWS_PB + w * 4;
    const int tt = tloc0 + (lane & 3);

    int pos = 0;
    #pragma unroll
    for (int step = NN >> 1; step >= 1; step >>= 1) {
        int np = pos + step;
        if (s_cum[np - 1] <= tt) pos = np;
    }
    const int idx = pos < (NN - 1) ? pos : (NN - 1);
    const int meta_mine = (tt >= total) ? -1 : (b * NN + idx) * D4;

    int m[4];
    #pragma unroll
    for (int r = 0; r < 4; r++) m[r] = __shfl_sync(0xFFFFFFFFu, meta_mine, r);

    // ---- mask: threads 0..31 write this block's 32 mask values ----
    if (write_mask && tid < ROWS_PB) {
        const int tm = seg * ROWS_PB + tid;
        mask_out[b * ML + tm] = (float)(tm >= total);
    }

    // ---- loads with warp-uniform dedup: rows 0,2 always load; 1,3 reuse
    //      their predecessor's registers when the source row matches. ----
    const float4 z = make_float4(0.f, 0.f, 0.f, 0.f);
    float4 v[12];

    // row 0
    if (m[0] >= 0) {
        v[0] = x4[m[0] + lane]; v[1] = x4[m[0] + lane + 32]; v[2] = x4[m[0] + lane + 64];
    } else { v[0] = z; v[1] = z; v[2] = z; }
    // row 2 (independent of row 0 -> 2-way MLP)
    if (m[2] >= 0) {
        v[6] = x4[m[2] + lane]; v[7] = x4[m[2] + lane + 32]; v[8] = x4[m[2] + lane + 64];
    } else { v[6] = z; v[7] = z; v[8] = z; }

    // row 1: reuse row 0 if same source
    if (m[1] == m[0]) {
        v[3] = v[0]; v[4] = v[1]; v[5] = v[2];
    } else if (m[1] >= 0) {
        v[3] = x4[m[1] + lane]; v[4] = x4[m[1] + lane + 32]; v[5] = x4[m[1] + lane + 64];
    } else { v[3] = z; v[4] = z; v[5] = z; }

    // row 3: reuse row 2 if same source
    if (m[3] == m[2]) {
        v[9] = v[6]; v[10] = v[7]; v[11] = v[8];
    } else if (m[3] >= 0) {
        v[9] = x4[m[3] + lane]; v[10] = x4[m[3] + lane + 32]; v[11] = x4[m[3] + lane + 64];
    } else { v[9] = z; v[10] = z; v[11] = z; }

    // ---- streaming stores ----
    float4* d = out4 + ((size_t)b * ML + tloc0) * D4;
    #pragma unroll
    for (int r = 0; r < 4; r++) {
        __stcs(d + lane,      v[r * 3 + 0]);
        __stcs(d + lane + 32, v[r * 3 + 1]);
        __stcs(d + lane + 64, v[r * 3 + 2]);
        d += D4;
    }
}

extern "C" void kernel_launch(void* const* d_in, const int* in_sizes, int n_in,
                              void* d_out, int out_size) {
    const float* x   = (const float*)d_in[0];
    const int*   dur = (const int*)d_in[1];
    float*       out = (float*)d_out;

    const long long out_elems  = (long long)NROWS * DD;
    const long long mask_elems = (long long)NROWS;
    int write_mask = ((long long)out_size >= out_elems + mask_elems) ? 1 : 0;
    float* mask_out = write_mask ? (out + out_elems) : nullptr;

    fused_kernel<<<BB * BPB, TPB>>>((const float4*)x, (float4*)out, dur,
                                    mask_out, write_mask);
}